// round 3
// baseline (speedup 1.0000x reference)
#include <cuda_runtime.h>
#include <cuda_bf16.h>

// Problem constants (fixed by the dataset)
#define NN 100000
#define EE 1000000
#define FIN 64
#define HH 64
#define GG 512
#define CC 2

// Scratch (no allocations allowed) — kernels reference these directly
__device__ float g_bufA[NN * HH];   // agg / layer output
__device__ float g_bufB[NN * HH];   // xw
__device__ float g_dinv[NN];
__device__ float g_deg[NN];
__device__ float g_norm[EE];
__device__ float g_pool[GG * HH];
__device__ float g_cnt[GG];

// ---------------------------------------------------------------------------
// 0) zero accumulators (must happen every call: graph replays)
__global__ void k_zero() {
    int i = blockIdx.x * blockDim.x + threadIdx.x;
    if (i < NN) g_deg[i] = 0.f;
    if (i < GG) g_cnt[i] = 0.f;
    if (i < GG * HH) g_pool[i] = 0.f;
}

// 1) deg[dst] += w[e]
__global__ void k_deg(const int* __restrict__ dst, const float* __restrict__ w) {
    int e = blockIdx.x * blockDim.x + threadIdx.x;
    if (e < EE) atomicAdd(&g_deg[dst[e]], w[e]);
}

// 2) dinv = rsqrt(deg + 2); also count nodes per graph
__global__ void k_dinv(const int* __restrict__ batch) {
    int n = blockIdx.x * blockDim.x + threadIdx.x;
    if (n < NN) {
        float d = g_deg[n] + 2.0f;          // SELF_LOOP_W = 2, always > 0
        g_dinv[n] = rsqrtf(d);
        atomicAdd(&g_cnt[batch[n]], 1.0f);
    }
}

// 3) norm[e] = dinv[src]*w*dinv[dst]
__global__ void k_norm(const int* __restrict__ src, const int* __restrict__ dst,
                       const float* __restrict__ w) {
    int e = blockIdx.x * blockDim.x + threadIdx.x;
    if (e < EE) g_norm[e] = g_dinv[src[e]] * w[e] * g_dinv[dst[e]];
}

// 4) GEMM: g_bufB[row,:] = act(in)[row,:] @ W
//    use_ext: read from xext (first layer), else read g_bufA with ReLU.
__global__ __launch_bounds__(256) void k_gemm64(const float* __restrict__ xext,
                                                const float* __restrict__ W,
                                                int use_ext) {
    __shared__ float Ws[64 * 64];
    __shared__ float Xs[4][64];
    int tid = threadIdx.x;                 // 256 threads: 4 rows x 64 cols
    for (int i = tid; i < 64 * 64; i += 256) Ws[i] = W[i];
    int rl = tid >> 6;
    int col = tid & 63;
    int row = blockIdx.x * 4 + rl;
    float v = 0.f;
    if (row < NN) {
        if (use_ext) v = xext[row * 64 + col];
        else         v = fmaxf(g_bufA[row * 64 + col], 0.f);
    }
    Xs[rl][col] = v;
    __syncthreads();
    if (row < NN) {
        float acc = 0.f;
#pragma unroll
        for (int k = 0; k < 64; k++) acc += Xs[rl][k] * Ws[k * 64 + col];
        g_bufB[row * 64 + col] = acc;
    }
}

// 5) agg init: g_bufA = 2*dinv^2 * g_bufB + b   (self-loop term + bias)
__global__ __launch_bounds__(256) void k_agg_init(const float* __restrict__ b) {
    int i = blockIdx.x * blockDim.x + threadIdx.x;
    if (i < NN * HH) {
        int n = i >> 6, j = i & 63;
        float di = g_dinv[n];
        g_bufA[i] = 2.0f * di * di * g_bufB[i] + b[j];
    }
}

// 6) edge scatter: g_bufA[dst] += norm * g_bufB[src]  (warp per edge, 2 cols/lane)
__global__ __launch_bounds__(256) void k_scatter(const int* __restrict__ src,
                                                 const int* __restrict__ dst) {
    long long idx = (long long)blockIdx.x * blockDim.x + threadIdx.x;
    int e = (int)(idx >> 5);
    if (e >= EE) return;
    int lane = (int)(idx & 31);
    float nrm = g_norm[e];
    int s = src[e], d = dst[e];
    float2 v = *(const float2*)(g_bufB + (size_t)s * 64 + lane * 2);
    atomicAdd(&g_bufA[(size_t)d * 64 + lane * 2 + 0], nrm * v.x);
    atomicAdd(&g_bufA[(size_t)d * 64 + lane * 2 + 1], nrm * v.y);
}

// 7) pool: g_pool[batch[n]] += g_bufA[n]
__global__ __launch_bounds__(256) void k_pool(const int* __restrict__ batch) {
    int i = blockIdx.x * blockDim.x + threadIdx.x;
    if (i < NN * HH) {
        int n = i >> 6, j = i & 63;
        atomicAdd(&g_pool[batch[n] * 64 + j], g_bufA[i]);
    }
}

// 8) final: out[g,c] = bl[c] + (g_pool[g,:]/max(cnt,1)) @ Wl[:,c]
__global__ void k_final(const float* __restrict__ Wl, const float* __restrict__ bl,
                        float* __restrict__ out) {
    int i = blockIdx.x * blockDim.x + threadIdx.x;   // G*C threads
    if (i < GG * CC) {
        int g = i / CC, c = i % CC;
        float inv = 1.0f / fmaxf(g_cnt[g], 1.0f);
        float acc = 0.f;
#pragma unroll
        for (int j = 0; j < 64; j++) acc += g_pool[g * 64 + j] * Wl[j * CC + c];
        out[i] = acc * inv + bl[c];
    }
}

extern "C" void kernel_launch(void* const* d_in, const int* in_sizes, int n_in,
                              void* d_out, int out_size) {
    const float* x    = (const float*)d_in[0];
    const int*   ei   = (const int*)d_in[1];     // [2,E]
    const float* w    = (const float*)d_in[2];
    const int*   batch= (const int*)d_in[3];
    const float* W1   = (const float*)d_in[4];
    const float* b1   = (const float*)d_in[5];
    const float* W2   = (const float*)d_in[6];
    const float* b2   = (const float*)d_in[7];
    const float* W3   = (const float*)d_in[8];
    const float* b3   = (const float*)d_in[9];
    const float* Wl   = (const float*)d_in[10];
    const float* bl   = (const float*)d_in[11];
    float* out = (float*)d_out;

    const int* src = ei;
    const int* dst = ei + EE;

    // precompute normalization (reused by all 3 layers)
    k_zero<<<(NN + 255) / 256, 256>>>();
    k_deg<<<(EE + 255) / 256, 256>>>(dst, w);
    k_dinv<<<(NN + 255) / 256, 256>>>(batch);
    k_norm<<<(EE + 255) / 256, 256>>>(src, dst, w);

    const long long scat_threads = (long long)EE * 32;
    const int scat_blocks = (int)((scat_threads + 255) / 256);
    const int nh_blocks = (NN * HH + 255) / 256;

    // layer 1
    k_gemm64<<<(NN + 3) / 4, 256>>>(x, W1, 1);
    k_agg_init<<<nh_blocks, 256>>>(b1);
    k_scatter<<<scat_blocks, 256>>>(src, dst);
    // layer 2 (relu on input fused into gemm)
    k_gemm64<<<(NN + 3) / 4, 256>>>(x, W2, 0);
    k_agg_init<<<nh_blocks, 256>>>(b2);
    k_scatter<<<scat_blocks, 256>>>(src, dst);
    // layer 3
    k_gemm64<<<(NN + 3) / 4, 256>>>(x, W3, 0);
    k_agg_init<<<nh_blocks, 256>>>(b3);
    k_scatter<<<scat_blocks, 256>>>(src, dst);

    // mean pool + classifier
    k_pool<<<nh_blocks, 256>>>(batch);
    k_final<<<(GG * CC + 255) / 256, 256>>>(Wl, bl, out);
}

// round 5
// speedup vs baseline: 1.3039x; 1.3039x over previous
#include <cuda_runtime.h>
#include <cuda_bf16.h>

#define NN 100000
#define EE 1000000
#define HH 64
#define GG 512
#define CC 2

// Scratch (device globals; no allocations allowed)
__device__ float g_bufA[NN * HH];      // layer output (pre-ReLU)
__device__ float g_bufB[NN * HH];      // xw = act(h) @ W
__device__ float g_dinv[NN];
__device__ float g_deg[NN];
__device__ int   g_ecnt[NN];           // in-degree (edge count) per dst
__device__ int   g_fill[NN];           // CSR fill cursors
__device__ int   g_rowptr[NN + 1];
__device__ int   g_csrc[EE];           // CSR: src node per edge (dst-sorted)
__device__ float g_cval[EE];           // CSR: norm per edge
__device__ float g_cnt[GG];            // nodes per graph
__device__ float g_plog[GG * CC];      // pooled logits accumulator

// ---------------------------------------------------------------------------
// 0) zero accumulators (graph replays -> must re-zero every call)
__global__ __launch_bounds__(256) void k_zero() {
    int i = blockIdx.x * blockDim.x + threadIdx.x;
    if (i < NN) { g_deg[i] = 0.f; g_ecnt[i] = 0; g_fill[i] = 0; }
    if (i < GG) g_cnt[i] = 0.f;
    if (i < GG * CC) g_plog[i] = 0.f;
}

// 1) weighted degree + edge count per dst
__global__ __launch_bounds__(256) void k_deg(const int* __restrict__ dst,
                                             const float* __restrict__ w) {
    int e = blockIdx.x * blockDim.x + threadIdx.x;
    if (e < EE) {
        int d = dst[e];
        atomicAdd(&g_deg[d], w[e]);
        atomicAdd(&g_ecnt[d], 1);
    }
}

// 2) dinv = rsqrt(deg + 2); nodes-per-graph count
__global__ __launch_bounds__(256) void k_dinv(const int* __restrict__ batch) {
    int n = blockIdx.x * blockDim.x + threadIdx.x;
    if (n < NN) {
        g_dinv[n] = rsqrtf(g_deg[n] + 2.0f);   // SELF_LOOP_W=2, always > 0
        atomicAdd(&g_cnt[batch[n]], 1.0f);
    }
}

// 3) exclusive prefix sum of g_ecnt -> g_rowptr (single block, 1024 threads)
__global__ __launch_bounds__(1024) void k_scan() {
    __shared__ int sh[1024];
    const int CH = (NN + 1023) / 1024;         // 98
    int t = threadIdx.x;
    int beg = t * CH;
    int s = 0;
#pragma unroll 1
    for (int i = 0; i < CH; i++) {
        int n = beg + i;
        if (n < NN) s += g_ecnt[n];
    }
    sh[t] = s;
    __syncthreads();
    for (int off = 1; off < 1024; off <<= 1) {
        int v = (t >= off) ? sh[t - off] : 0;
        __syncthreads();
        sh[t] += v;
        __syncthreads();
    }
    int excl = (t == 0) ? 0 : sh[t - 1];
#pragma unroll 1
    for (int i = 0; i < CH; i++) {
        int n = beg + i;
        if (n < NN) { g_rowptr[n] = excl; excl += g_ecnt[n]; }
    }
    if (t == 1023) g_rowptr[NN] = sh[1023];
}

// 4) fill CSR: for each edge, compute norm and place (src,norm) in dst's row
__global__ __launch_bounds__(256) void k_fill(const int* __restrict__ src,
                                              const int* __restrict__ dst,
                                              const float* __restrict__ w) {
    int e = blockIdx.x * blockDim.x + threadIdx.x;
    if (e < EE) {
        int s = src[e], d = dst[e];
        float nrm = g_dinv[s] * w[e] * g_dinv[d];
        int pos = g_rowptr[d] + atomicAdd(&g_fill[d], 1);
        g_csrc[pos] = s;
        g_cval[pos] = nrm;
    }
}

// 5) GEMM: g_bufB = act(in) @ W.  64 rows per block (W loaded once per block).
__global__ __launch_bounds__(256) void k_gemm64(const float* __restrict__ xext,
                                                const float* __restrict__ W,
                                                int use_ext) {
    __shared__ float Ws[64 * 64];
    __shared__ float Xs[4][64];
    int tid = threadIdx.x;
    for (int i = tid; i < 64 * 64; i += 256) Ws[i] = W[i];
    int rl = tid >> 6, col = tid & 63;
    int base = blockIdx.x * 64;
#pragma unroll 1
    for (int it = 0; it < 16; ++it) {
        int row = base + it * 4 + rl;
        float v = 0.f;
        if (row < NN) {
            v = use_ext ? xext[row * 64 + col]
                        : fmaxf(g_bufA[row * 64 + col], 0.f);
        }
        __syncthreads();           // Ws ready (it=0) / Xs consumers done (it>0)
        Xs[rl][col] = v;
        __syncthreads();
        if (row < NN) {
            float acc = 0.f;
#pragma unroll
            for (int k = 0; k < 64; k++) acc += Xs[rl][k] * Ws[k * 64 + col];
            g_bufB[row * 64 + col] = acc;
        }
    }
}

// 6) gather: warp per dst node, 2 cols per lane.  Epilogue adds self-loop+bias.
//    layer3: fold h @ Wl into per-graph logit atomics instead of writing h.
__global__ __launch_bounds__(256) void k_gather(const float* __restrict__ bias,
                                                const int* __restrict__ batch,
                                                const float* __restrict__ Wl,
                                                int layer3) {
    int wid = (blockIdx.x * blockDim.x + threadIdx.x) >> 5;
    int lane = threadIdx.x & 31;
    if (wid >= NN) return;
    int n = wid;
    int beg = g_rowptr[n], end = g_rowptr[n + 1];
    float a0 = 0.f, a1 = 0.f, c0a = 0.f, c1a = 0.f;
    int i = beg;
    for (; i + 1 < end; i += 2) {
        int s0 = g_csrc[i], s1 = g_csrc[i + 1];
        float v0 = g_cval[i], v1 = g_cval[i + 1];
        float2 x0 = *(const float2*)(g_bufB + (size_t)s0 * 64 + lane * 2);
        float2 x1 = *(const float2*)(g_bufB + (size_t)s1 * 64 + lane * 2);
        a0 += v0 * x0.x; a1 += v0 * x0.y;
        c0a += v1 * x1.x; c1a += v1 * x1.y;
    }
    if (i < end) {
        int s = g_csrc[i]; float v = g_cval[i];
        float2 xv = *(const float2*)(g_bufB + (size_t)s * 64 + lane * 2);
        a0 += v * xv.x; a1 += v * xv.y;
    }
    a0 += c0a; a1 += c1a;
    float di = g_dinv[n];
    float sl = 2.0f * di * di;
    float2 xw = *(const float2*)(g_bufB + (size_t)n * 64 + lane * 2);
    a0 += sl * xw.x + bias[lane * 2 + 0];
    a1 += sl * xw.y + bias[lane * 2 + 1];
    if (!layer3) {
        *(float2*)(g_bufA + (size_t)n * 64 + lane * 2) = make_float2(a0, a1);
    } else {
        int j0 = lane * 2, j1 = lane * 2 + 1;
        float c0 = a0 * Wl[j0 * CC + 0] + a1 * Wl[j1 * CC + 0];
        float c1 = a0 * Wl[j0 * CC + 1] + a1 * Wl[j1 * CC + 1];
#pragma unroll
        for (int off = 16; off; off >>= 1) {
            c0 += __shfl_xor_sync(0xffffffffu, c0, off);
            c1 += __shfl_xor_sync(0xffffffffu, c1, off);
        }
        if (lane == 0) {
            int g = batch[n];
            atomicAdd(&g_plog[g * CC + 0], c0);
            atomicAdd(&g_plog[g * CC + 1], c1);
        }
    }
}

// 7) final: out = plog / max(cnt,1) + bl
__global__ __launch_bounds__(256) void k_final(const float* __restrict__ bl,
                                               float* __restrict__ out) {
    int i = blockIdx.x * blockDim.x + threadIdx.x;
    if (i < GG * CC) {
        int g = i / CC, c = i % CC;
        out[i] = g_plog[i] / fmaxf(g_cnt[g], 1.0f) + bl[c];
    }
}

extern "C" void kernel_launch(void* const* d_in, const int* in_sizes, int n_in,
                              void* d_out, int out_size) {
    const float* x     = (const float*)d_in[0];
    const int*   ei    = (const int*)d_in[1];    // [2,E]
    const float* w     = (const float*)d_in[2];
    const int*   batch = (const int*)d_in[3];
    const float* W1    = (const float*)d_in[4];
    const float* b1    = (const float*)d_in[5];
    const float* W2    = (const float*)d_in[6];
    const float* b2    = (const float*)d_in[7];
    const float* W3    = (const float*)d_in[8];
    const float* b3    = (const float*)d_in[9];
    const float* Wl    = (const float*)d_in[10];
    const float* bl    = (const float*)d_in[11];
    float* out = (float*)d_out;

    const int* src = ei;
    const int* dst = ei + EE;

    const int eb = (EE + 255) / 256;
    const int nb = (NN + 255) / 256;
    const int gemm_b = (NN + 63) / 64;
    const int gath_b = (NN * 32 + 255) / 256;

    // CSR + normalization build (reused by all 3 layers)
    k_zero<<<nb, 256>>>();
    k_deg<<<eb, 256>>>(dst, w);
    k_dinv<<<nb, 256>>>(batch);
    k_scan<<<1, 1024>>>();
    k_fill<<<eb, 256>>>(src, dst, w);

    // layer 1
    k_gemm64<<<gemm_b, 256>>>(x, W1, 1);
    k_gather<<<gath_b, 256>>>(b1, batch, Wl, 0);
    // layer 2
    k_gemm64<<<gemm_b, 256>>>(x, W2, 0);
    k_gather<<<gath_b, 256>>>(b2, batch, Wl, 0);
    // layer 3 (fused pool + classifier partials)
    k_gemm64<<<gemm_b, 256>>>(x, W3, 0);
    k_gather<<<gath_b, 256>>>(b3, batch, Wl, 1);

    k_final<<<(GG * CC + 255) / 256, 256>>>(bl, out);
}

// round 6
// speedup vs baseline: 1.5736x; 1.2068x over previous
#include <cuda_runtime.h>
#include <cuda_bf16.h>

#define NN 100000
#define EE 1000000
#define HH 64
#define GG 512
#define CC 2

#define SCAN_T 512
#define SCAN_NB ((NN + SCAN_T - 1) / SCAN_T)   // 196

// Scratch (device globals; no allocations allowed)
__device__ float g_bufA[NN * HH];      // layer output (pre-ReLU)
__device__ float g_bufB[NN * HH];      // xw = act(h) @ W
__device__ float g_dinv[NN];
__device__ float g_deg[NN];
__device__ int   g_ecnt[NN];           // in-degree (edge count) per dst
__device__ int   g_fill[NN];           // CSR fill cursors
__device__ int   g_rowptr[NN + 1];
__device__ int   g_csrc[EE];           // CSR: src node per edge (dst-sorted)
__device__ float g_cval[EE];           // CSR: norm per edge
__device__ float g_cnt[GG];            // nodes per graph
__device__ float g_plog[GG * CC];      // pooled logits accumulator
__device__ int   g_bsum[SCAN_NB];
__device__ int   g_boff[SCAN_NB];

// ---------------------------------------------------------------------------
// 0) zero accumulators (graph replays -> must re-zero every call)
__global__ __launch_bounds__(256) void k_zero() {
    int i = blockIdx.x * blockDim.x + threadIdx.x;
    if (i < NN) { g_deg[i] = 0.f; g_ecnt[i] = 0; g_fill[i] = 0; }
    if (i < GG) g_cnt[i] = 0.f;
    if (i < GG * CC) g_plog[i] = 0.f;
}

// 1) weighted degree + edge count per dst
__global__ __launch_bounds__(256) void k_deg(const int* __restrict__ dst,
                                             const float* __restrict__ w) {
    int e = blockIdx.x * blockDim.x + threadIdx.x;
    if (e < EE) {
        int d = dst[e];
        atomicAdd(&g_deg[d], w[e]);
        atomicAdd(&g_ecnt[d], 1);
    }
}

// 2) dinv = rsqrt(deg + 2); nodes-per-graph count
__global__ __launch_bounds__(256) void k_dinv(const int* __restrict__ batch) {
    int n = blockIdx.x * blockDim.x + threadIdx.x;
    if (n < NN) {
        g_dinv[n] = rsqrtf(g_deg[n] + 2.0f);   // SELF_LOOP_W=2, always > 0
        atomicAdd(&g_cnt[batch[n]], 1.0f);
    }
}

// 3a) per-block reduction of ecnt -> g_bsum[block]
__global__ __launch_bounds__(SCAN_T) void k_scanA() {
    __shared__ int sh[SCAN_T / 32];
    int b = blockIdx.x, t = threadIdx.x;
    int i = b * SCAN_T + t;
    int v = (i < NN) ? g_ecnt[i] : 0;
#pragma unroll
    for (int off = 16; off; off >>= 1) v += __shfl_xor_sync(~0u, v, off);
    if ((t & 31) == 0) sh[t >> 5] = v;
    __syncthreads();
    if (t < SCAN_T / 32) {
        int s = sh[t];
#pragma unroll
        for (int off = SCAN_T / 64; off; off >>= 1)
            s += __shfl_xor_sync(0xffffu, s, off);
        if (t == 0) g_bsum[b] = s;
    }
}

// 3b) exclusive scan of the 196 block sums (single tiny block)
__global__ __launch_bounds__(256) void k_scanB() {
    __shared__ int sh[256];
    int t = threadIdx.x;
    int v = (t < SCAN_NB) ? g_bsum[t] : 0;
    sh[t] = v;
    __syncthreads();
    for (int off = 1; off < 256; off <<= 1) {
        int u = (t >= off) ? sh[t - off] : 0;
        __syncthreads();
        sh[t] += u;
        __syncthreads();
    }
    if (t < SCAN_NB) g_boff[t] = sh[t] - v;        // exclusive block offset
    if (t == 255) g_rowptr[NN] = sh[255];          // grand total (= EE)
}

// 3c) per-block local exclusive scan + block offset -> rowptr
__global__ __launch_bounds__(SCAN_T) void k_scanC() {
    __shared__ int sh[SCAN_T];
    int b = blockIdx.x, t = threadIdx.x;
    int i = b * SCAN_T + t;
    int v = (i < NN) ? g_ecnt[i] : 0;
    sh[t] = v;
    __syncthreads();
    for (int off = 1; off < SCAN_T; off <<= 1) {
        int u = (t >= off) ? sh[t - off] : 0;
        __syncthreads();
        sh[t] += u;
        __syncthreads();
    }
    if (i < NN) g_rowptr[i] = g_boff[b] + sh[t] - v;
}

// 4) fill CSR: for each edge, compute norm and place (src,norm) in dst's row
__global__ __launch_bounds__(256) void k_fill(const int* __restrict__ src,
                                              const int* __restrict__ dst,
                                              const float* __restrict__ w) {
    int e = blockIdx.x * blockDim.x + threadIdx.x;
    if (e < EE) {
        int s = src[e], d = dst[e];
        float nrm = g_dinv[s] * w[e] * g_dinv[d];
        int pos = g_rowptr[d] + atomicAdd(&g_fill[d], 1);
        g_csrc[pos] = s;
        g_cval[pos] = nrm;
    }
}

// 5) GEMM: g_bufB = act(in) @ W.  64 rows per block (W loaded once per block).
__global__ __launch_bounds__(256) void k_gemm64(const float* __restrict__ xext,
                                                const float* __restrict__ W,
                                                int use_ext) {
    __shared__ float Ws[64 * 64];
    __shared__ float Xs[4][64];
    int tid = threadIdx.x;
    for (int i = tid; i < 64 * 64; i += 256) Ws[i] = W[i];
    int rl = tid >> 6, col = tid & 63;
    int base = blockIdx.x * 64;
#pragma unroll 1
    for (int it = 0; it < 16; ++it) {
        int row = base + it * 4 + rl;
        float v = 0.f;
        if (row < NN) {
            v = use_ext ? xext[row * 64 + col]
                        : fmaxf(g_bufA[row * 64 + col], 0.f);
        }
        __syncthreads();           // Ws ready (it=0) / Xs consumers done (it>0)
        Xs[rl][col] = v;
        __syncthreads();
        if (row < NN) {
            float acc = 0.f;
#pragma unroll
            for (int k = 0; k < 64; k++) acc += Xs[rl][k] * Ws[k * 64 + col];
            g_bufB[row * 64 + col] = acc;
        }
    }
}

// 6) gather: warp per dst node, 2 cols per lane, 4-edge ILP.
//    Epilogue adds self-loop + bias. layer3: fold h @ Wl into per-graph logits.
__global__ __launch_bounds__(256) void k_gather(const float* __restrict__ bias,
                                                const int* __restrict__ batch,
                                                const float* __restrict__ Wl,
                                                int layer3) {
    int wid = (blockIdx.x * blockDim.x + threadIdx.x) >> 5;
    int lane = threadIdx.x & 31;
    if (wid >= NN) return;
    int n = wid;
    int beg = g_rowptr[n], end = g_rowptr[n + 1];
    float a0 = 0.f, a1 = 0.f, b0 = 0.f, b1 = 0.f;
    float c0 = 0.f, c1 = 0.f, d0 = 0.f, d1 = 0.f;
    int i = beg;
    for (; i + 3 < end; i += 4) {
        int s0 = g_csrc[i],     s1 = g_csrc[i + 1];
        int s2 = g_csrc[i + 2], s3 = g_csrc[i + 3];
        float v0 = g_cval[i],     v1 = g_cval[i + 1];
        float v2 = g_cval[i + 2], v3 = g_cval[i + 3];
        float2 x0 = *(const float2*)(g_bufB + (size_t)s0 * 64 + lane * 2);
        float2 x1 = *(const float2*)(g_bufB + (size_t)s1 * 64 + lane * 2);
        float2 x2 = *(const float2*)(g_bufB + (size_t)s2 * 64 + lane * 2);
        float2 x3 = *(const float2*)(g_bufB + (size_t)s3 * 64 + lane * 2);
        a0 += v0 * x0.x; a1 += v0 * x0.y;
        b0 += v1 * x1.x; b1 += v1 * x1.y;
        c0 += v2 * x2.x; c1 += v2 * x2.y;
        d0 += v3 * x3.x; d1 += v3 * x3.y;
    }
    for (; i < end; i++) {
        int s = g_csrc[i]; float v = g_cval[i];
        float2 xv = *(const float2*)(g_bufB + (size_t)s * 64 + lane * 2);
        a0 += v * xv.x; a1 += v * xv.y;
    }
    a0 += b0 + c0 + d0;
    a1 += b1 + c1 + d1;
    float di = g_dinv[n];
    float sl = 2.0f * di * di;
    float2 xw = *(const float2*)(g_bufB + (size_t)n * 64 + lane * 2);
    a0 += sl * xw.x + bias[lane * 2 + 0];
    a1 += sl * xw.y + bias[lane * 2 + 1];
    if (!layer3) {
        *(float2*)(g_bufA + (size_t)n * 64 + lane * 2) = make_float2(a0, a1);
    } else {
        int j0 = lane * 2, j1 = lane * 2 + 1;
        float l0 = a0 * Wl[j0 * CC + 0] + a1 * Wl[j1 * CC + 0];
        float l1 = a0 * Wl[j0 * CC + 1] + a1 * Wl[j1 * CC + 1];
#pragma unroll
        for (int off = 16; off; off >>= 1) {
            l0 += __shfl_xor_sync(0xffffffffu, l0, off);
            l1 += __shfl_xor_sync(0xffffffffu, l1, off);
        }
        if (lane == 0) {
            int g = batch[n];
            atomicAdd(&g_plog[g * CC + 0], l0);
            atomicAdd(&g_plog[g * CC + 1], l1);
        }
    }
}

// 7) final: out = plog / max(cnt,1) + bl
__global__ __launch_bounds__(256) void k_final(const float* __restrict__ bl,
                                               float* __restrict__ out) {
    int i = blockIdx.x * blockDim.x + threadIdx.x;
    if (i < GG * CC) {
        int g = i / CC, c = i % CC;
        out[i] = g_plog[i] / fmaxf(g_cnt[g], 1.0f) + bl[c];
    }
}

extern "C" void kernel_launch(void* const* d_in, const int* in_sizes, int n_in,
                              void* d_out, int out_size) {
    const float* x     = (const float*)d_in[0];
    const int*   ei    = (const int*)d_in[1];    // [2,E]
    const float* w     = (const float*)d_in[2];
    const int*   batch = (const int*)d_in[3];
    const float* W1    = (const float*)d_in[4];
    const float* b1    = (const float*)d_in[5];
    const float* W2    = (const float*)d_in[6];
    const float* b2    = (const float*)d_in[7];
    const float* W3    = (const float*)d_in[8];
    const float* b3    = (const float*)d_in[9];
    const float* Wl    = (const float*)d_in[10];
    const float* bl    = (const float*)d_in[11];
    float* out = (float*)d_out;

    const int* src = ei;
    const int* dst = ei + EE;

    const int eb = (EE + 255) / 256;
    const int nb = (NN + 255) / 256;
    const int gemm_b = (NN + 63) / 64;
    const int gath_b = (NN * 32 + 255) / 256;

    // CSR + normalization build (reused by all 3 layers)
    k_zero<<<nb, 256>>>();
    k_deg<<<eb, 256>>>(dst, w);
    k_dinv<<<nb, 256>>>(batch);
    k_scanA<<<SCAN_NB, SCAN_T>>>();
    k_scanB<<<1, 256>>>();
    k_scanC<<<SCAN_NB, SCAN_T>>>();
    k_fill<<<eb, 256>>>(src, dst, w);

    // layer 1
    k_gemm64<<<gemm_b, 256>>>(x, W1, 1);
    k_gather<<<gath_b, 256>>>(b1, batch, Wl, 0);
    // layer 2
    k_gemm64<<<gemm_b, 256>>>(x, W2, 0);
    k_gather<<<gath_b, 256>>>(b2, batch, Wl, 0);
    // layer 3 (fused pool + classifier partials)
    k_gemm64<<<gemm_b, 256>>>(x, W3, 0);
    k_gather<<<gath_b, 256>>>(b3, batch, Wl, 1);

    k_final<<<(GG * CC + 255) / 256, 256>>>(bl, out);
}

// round 9
// speedup vs baseline: 2.1756x; 1.3826x over previous
#include <cuda_runtime.h>
#include <cuda_bf16.h>

#define NN 100000
#define EE 1000000
#define HH 64
#define GG 512
#define CC 2

#define SCAN_T 512
#define SCAN_NB ((NN + SCAN_T - 1) / SCAN_T)   // 196

// Scratch (device globals; no allocations allowed)
__device__ float g_bufA[NN * HH];
__device__ float g_bufB[NN * HH];
__device__ float g_dinv[NN];
__device__ float g_deg[NN];
__device__ int   g_ecnt[NN];
__device__ int   g_fill[NN];
__device__ int   g_rowptr[NN + 1];
__device__ int   g_csrc[EE];
__device__ float g_cval[EE];
__device__ float g_cnt[GG];
__device__ float g_plog[GG * CC];
__device__ int   g_bsum[SCAN_NB];
__device__ int   g_boff[SCAN_NB];

// ---------------------------------------------------------------------------
__global__ __launch_bounds__(256) void k_zero() {
    int i = blockIdx.x * blockDim.x + threadIdx.x;
    if (i < NN) { g_deg[i] = 0.f; g_ecnt[i] = 0; g_fill[i] = 0; }
    if (i < GG) g_cnt[i] = 0.f;
    if (i < GG * CC) g_plog[i] = 0.f;
}

__global__ __launch_bounds__(256) void k_deg(const int* __restrict__ dst,
                                             const float* __restrict__ w) {
    int e = blockIdx.x * blockDim.x + threadIdx.x;
    if (e < EE) {
        int d = dst[e];
        atomicAdd(&g_deg[d], w[e]);
        atomicAdd(&g_ecnt[d], 1);
    }
}

__global__ __launch_bounds__(256) void k_dinv(const int* __restrict__ batch) {
    int n = blockIdx.x * blockDim.x + threadIdx.x;
    if (n < NN) {
        g_dinv[n] = rsqrtf(g_deg[n] + 2.0f);
        atomicAdd(&g_cnt[batch[n]], 1.0f);
    }
}

// scan: per-block reduce -> scan of partials -> local scan + offset
__global__ __launch_bounds__(SCAN_T) void k_scanA() {
    __shared__ int sh[SCAN_T / 32];
    int b = blockIdx.x, t = threadIdx.x;
    int i = b * SCAN_T + t;
    int v = (i < NN) ? g_ecnt[i] : 0;
#pragma unroll
    for (int off = 16; off; off >>= 1) v += __shfl_xor_sync(~0u, v, off);
    if ((t & 31) == 0) sh[t >> 5] = v;
    __syncthreads();
    if (t < SCAN_T / 32) {
        int s = sh[t];
#pragma unroll
        for (int off = SCAN_T / 64; off; off >>= 1)
            s += __shfl_xor_sync(0xffffu, s, off);
        if (t == 0) g_bsum[b] = s;
    }
}

__global__ __launch_bounds__(256) void k_scanB() {
    __shared__ int sh[256];
    int t = threadIdx.x;
    int v = (t < SCAN_NB) ? g_bsum[t] : 0;
    sh[t] = v;
    __syncthreads();
    for (int off = 1; off < 256; off <<= 1) {
        int u = (t >= off) ? sh[t - off] : 0;
        __syncthreads();
        sh[t] += u;
        __syncthreads();
    }
    if (t < SCAN_NB) g_boff[t] = sh[t] - v;
    if (t == 255) g_rowptr[NN] = sh[255];
}

__global__ __launch_bounds__(SCAN_T) void k_scanC() {
    __shared__ int sh[SCAN_T];
    int b = blockIdx.x, t = threadIdx.x;
    int i = b * SCAN_T + t;
    int v = (i < NN) ? g_ecnt[i] : 0;
    sh[t] = v;
    __syncthreads();
    for (int off = 1; off < SCAN_T; off <<= 1) {
        int u = (t >= off) ? sh[t - off] : 0;
        __syncthreads();
        sh[t] += u;
        __syncthreads();
    }
    if (i < NN) g_rowptr[i] = g_boff[b] + sh[t] - v;
}

__global__ __launch_bounds__(256) void k_fill(const int* __restrict__ src,
                                              const int* __restrict__ dst,
                                              const float* __restrict__ w) {
    int e = blockIdx.x * blockDim.x + threadIdx.x;
    if (e < EE) {
        int s = src[e], d = dst[e];
        float nrm = g_dinv[s] * w[e] * g_dinv[d];
        int pos = g_rowptr[d] + atomicAdd(&g_fill[d], 1);
        g_csrc[pos] = s;
        g_cval[pos] = nrm;
    }
}

// ---------------------------------------------------------------------------
// GEMM: out = act(in) @ W.   64x64 tile per block, 4x4 micro-tile per thread.
__global__ __launch_bounds__(256) void k_gemm64(const float* __restrict__ in,
                                                const float* __restrict__ W,
                                                float* __restrict__ out,
                                                int relu) {
    __shared__ float Ws[64 * 64];
    __shared__ float XsT[64][65];          // transposed, padded (scalar reads)
    int tid = threadIdx.x;
    int base = blockIdx.x * 64;
    for (int i = tid; i < 4096; i += 256) Ws[i] = W[i];
    for (int idx = tid; idx < 4096; idx += 256) {
        int r = idx >> 6, c = idx & 63;
        int row = base + r;
        float v = 0.f;
        if (row < NN) {
            v = in[row * 64 + c];
            if (relu) v = fmaxf(v, 0.f);
        }
        XsT[c][r] = v;
    }
    __syncthreads();

    int tr = tid >> 4;      // 0..15 -> rows 4tr..4tr+3
    int tc = tid & 15;      // cols 4tc..4tc+3
    float acc[4][4] = {};
#pragma unroll
    for (int k = 0; k < 64; k++) {
        float x0 = XsT[k][tr * 4 + 0];     // scalar LDS (broadcast in warp)
        float x1 = XsT[k][tr * 4 + 1];
        float x2 = XsT[k][tr * 4 + 2];
        float x3 = XsT[k][tr * 4 + 3];
        float4 wv = *(const float4*)&Ws[k * 64 + tc * 4];
        acc[0][0] += x0 * wv.x; acc[0][1] += x0 * wv.y;
        acc[0][2] += x0 * wv.z; acc[0][3] += x0 * wv.w;
        acc[1][0] += x1 * wv.x; acc[1][1] += x1 * wv.y;
        acc[1][2] += x1 * wv.z; acc[1][3] += x1 * wv.w;
        acc[2][0] += x2 * wv.x; acc[2][1] += x2 * wv.y;
        acc[2][2] += x2 * wv.z; acc[2][3] += x2 * wv.w;
        acc[3][0] += x3 * wv.x; acc[3][1] += x3 * wv.y;
        acc[3][2] += x3 * wv.z; acc[3][3] += x3 * wv.w;
    }
#pragma unroll
    for (int i = 0; i < 4; i++) {
        int row = base + tr * 4 + i;
        if (row < NN) {
            float4 v = make_float4(acc[i][0], acc[i][1], acc[i][2], acc[i][3]);
            *(float4*)&out[row * 64 + tc * 4] = v;
        }
    }
}

// ---------------------------------------------------------------------------
// gather: warp per dst node; cooperative metadata + shuffle; 4-edge ILP.
__global__ __launch_bounds__(256) void k_gather(const float* __restrict__ xw,
                                                float* __restrict__ hout,
                                                const float* __restrict__ bias,
                                                const int* __restrict__ batch,
                                                const float* __restrict__ Wl,
                                                int layer3) {
    int wid = (blockIdx.x * blockDim.x + threadIdx.x) >> 5;
    int lane = threadIdx.x & 31;
    if (wid >= NN) return;
    int n = wid;
    int beg = g_rowptr[n], end = g_rowptr[n + 1];
    float a0 = 0.f, a1 = 0.f, b0 = 0.f, b1 = 0.f;
    float c0 = 0.f, c1 = 0.f, d0 = 0.f, d1 = 0.f;
    for (int cb = beg; cb < end; cb += 32) {
        int m = end - cb; if (m > 32) m = 32;
        int sreg = 0; float vreg = 0.f;
        if (lane < m) { sreg = g_csrc[cb + lane]; vreg = g_cval[cb + lane]; }
        int j = 0;
        for (; j + 3 < m; j += 4) {
            int s0 = __shfl_sync(~0u, sreg, j);
            int s1 = __shfl_sync(~0u, sreg, j + 1);
            int s2 = __shfl_sync(~0u, sreg, j + 2);
            int s3 = __shfl_sync(~0u, sreg, j + 3);
            float v0 = __shfl_sync(~0u, vreg, j);
            float v1 = __shfl_sync(~0u, vreg, j + 1);
            float v2 = __shfl_sync(~0u, vreg, j + 2);
            float v3 = __shfl_sync(~0u, vreg, j + 3);
            float2 x0 = *(const float2*)(xw + (size_t)s0 * 64 + lane * 2);
            float2 x1 = *(const float2*)(xw + (size_t)s1 * 64 + lane * 2);
            float2 x2 = *(const float2*)(xw + (size_t)s2 * 64 + lane * 2);
            float2 x3 = *(const float2*)(xw + (size_t)s3 * 64 + lane * 2);
            a0 += v0 * x0.x; a1 += v0 * x0.y;
            b0 += v1 * x1.x; b1 += v1 * x1.y;
            c0 += v2 * x2.x; c1 += v2 * x2.y;
            d0 += v3 * x3.x; d1 += v3 * x3.y;
        }
        for (; j < m; j++) {
            int s = __shfl_sync(~0u, sreg, j);
            float v = __shfl_sync(~0u, vreg, j);
            float2 xv = *(const float2*)(xw + (size_t)s * 64 + lane * 2);
            a0 += v * xv.x; a1 += v * xv.y;
        }
    }
    a0 += b0 + c0 + d0;
    a1 += b1 + c1 + d1;
    float di = g_dinv[n];
    float sl = 2.0f * di * di;
    float2 xwn = *(const float2*)(xw + (size_t)n * 64 + lane * 2);
    a0 += sl * xwn.x + bias[lane * 2 + 0];
    a1 += sl * xwn.y + bias[lane * 2 + 1];
    if (!layer3) {
        *(float2*)(hout + (size_t)n * 64 + lane * 2) = make_float2(a0, a1);
    } else {
        int j0 = lane * 2, j1 = lane * 2 + 1;
        float l0 = a0 * Wl[j0 * CC + 0] + a1 * Wl[j1 * CC + 0];
        float l1 = a0 * Wl[j0 * CC + 1] + a1 * Wl[j1 * CC + 1];
#pragma unroll
        for (int off = 16; off; off >>= 1) {
            l0 += __shfl_xor_sync(0xffffffffu, l0, off);
            l1 += __shfl_xor_sync(0xffffffffu, l1, off);
        }
        if (lane == 0) {
            int g = batch[n];
            atomicAdd(&g_plog[g * CC + 0], l0);
            atomicAdd(&g_plog[g * CC + 1], l1);
        }
    }
}

__global__ __launch_bounds__(256) void k_final(const float* __restrict__ bl,
                                               float* __restrict__ out) {
    int i = blockIdx.x * blockDim.x + threadIdx.x;
    if (i < GG * CC) {
        int g = i / CC, c = i % CC;
        out[i] = g_plog[i] / fmaxf(g_cnt[g], 1.0f) + bl[c];
    }
}

extern "C" void kernel_launch(void* const* d_in, const int* in_sizes, int n_in,
                              void* d_out, int out_size) {
    const float* x     = (const float*)d_in[0];
    const int*   ei    = (const int*)d_in[1];
    const float* w     = (const float*)d_in[2];
    const int*   batch = (const int*)d_in[3];
    const float* W1    = (const float*)d_in[4];
    const float* b1    = (const float*)d_in[5];
    const float* W2    = (const float*)d_in[6];
    const float* b2    = (const float*)d_in[7];
    const float* W3    = (const float*)d_in[8];
    const float* b3    = (const float*)d_in[9];
    const float* Wl    = (const float*)d_in[10];
    const float* bl    = (const float*)d_in[11];
    float* out = (float*)d_out;

    const int* src = ei;
    const int* dst = ei + EE;

    float* A;  cudaGetSymbolAddress((void**)&A, g_bufA);
    float* B;  cudaGetSymbolAddress((void**)&B, g_bufB);

    const int eb = (EE + 255) / 256;
    const int nb = (NN + 255) / 256;
    const int gemm_b = (NN + 63) / 64;
    const int gath_b = (NN * 32 + 255) / 256;

    // CSR + normalization build (reused by all 3 layers)
    k_zero<<<nb, 256>>>();
    k_deg<<<eb, 256>>>(dst, w);
    k_dinv<<<nb, 256>>>(batch);
    k_scanA<<<SCAN_NB, SCAN_T>>>();
    k_scanB<<<1, 256>>>();
    k_scanC<<<SCAN_NB, SCAN_T>>>();
    k_fill<<<eb, 256>>>(src, dst, w);

    // layer 1: xw=B, h1 -> A
    k_gemm64<<<gemm_b, 256>>>(x, W1, B, 0);
    k_gather<<<gath_b, 256>>>(B, A, b1, batch, Wl, 0);
    // layer 2: xw=B, h2 -> A
    k_gemm64<<<gemm_b, 256>>>(A, W2, B, 1);
    k_gather<<<gath_b, 256>>>(B, A, b2, batch, Wl, 0);
    // layer 3: xw=B, fused pool+classifier
    k_gemm64<<<gemm_b, 256>>>(A, W3, B, 1);
    k_gather<<<gath_b, 256>>>(B, A, b3, batch, Wl, 1);

    k_final<<<(GG * CC + 255) / 256, 256>>>(bl, out);
}

// round 10
// speedup vs baseline: 2.2943x; 1.0545x over previous
#include <cuda_runtime.h>
#include <cuda_bf16.h>

#define NN 100000
#define EE 1000000
#define HH 64
#define GG 512
#define CC 2

#define SCAN_T 512
#define SCAN_NB ((NN + SCAN_T - 1) / SCAN_T)   // 196

// Scratch (device globals; no allocations allowed)
__device__ float g_bufA[NN * HH];
__device__ float g_bufB[NN * HH];
__device__ float g_dinv[NN];
__device__ float g_deg[NN];
__device__ int   g_ecnt[NN];
__device__ int   g_fill[NN];
__device__ int   g_rowptr[NN + 1];
__device__ int2  g_cmeta[EE];          // (src, norm float bits) per edge
__device__ float g_cnt[GG];
__device__ float g_plog[GG * CC];
__device__ int   g_bsum[SCAN_NB];
__device__ int   g_boff[SCAN_NB];

// ---------------------------------------------------------------------------
__global__ __launch_bounds__(256) void k_zero() {
    int i = blockIdx.x * blockDim.x + threadIdx.x;
    if (i < NN) { g_deg[i] = 0.f; g_ecnt[i] = 0; g_fill[i] = 0; }
    if (i < GG) g_cnt[i] = 0.f;
    if (i < GG * CC) g_plog[i] = 0.f;
}

__global__ __launch_bounds__(256) void k_deg(const int* __restrict__ dst,
                                             const float* __restrict__ w) {
    int e = blockIdx.x * blockDim.x + threadIdx.x;
    if (e < EE) {
        int d = dst[e];
        atomicAdd(&g_deg[d], w[e]);
        atomicAdd(&g_ecnt[d], 1);
    }
}

__global__ __launch_bounds__(256) void k_dinv(const int* __restrict__ batch) {
    int n = blockIdx.x * blockDim.x + threadIdx.x;
    if (n < NN) {
        g_dinv[n] = rsqrtf(g_deg[n] + 2.0f);
        atomicAdd(&g_cnt[batch[n]], 1.0f);
    }
}

// scan: per-block reduce -> scan of partials -> local scan + offset
__global__ __launch_bounds__(SCAN_T) void k_scanA() {
    __shared__ int sh[SCAN_T / 32];
    int b = blockIdx.x, t = threadIdx.x;
    int i = b * SCAN_T + t;
    int v = (i < NN) ? g_ecnt[i] : 0;
#pragma unroll
    for (int off = 16; off; off >>= 1) v += __shfl_xor_sync(~0u, v, off);
    if ((t & 31) == 0) sh[t >> 5] = v;
    __syncthreads();
    if (t < SCAN_T / 32) {
        int s = sh[t];
#pragma unroll
        for (int off = SCAN_T / 64; off; off >>= 1)
            s += __shfl_xor_sync(0xffffu, s, off);
        if (t == 0) g_bsum[b] = s;
    }
}

__global__ __launch_bounds__(256) void k_scanB() {
    __shared__ int sh[256];
    int t = threadIdx.x;
    int v = (t < SCAN_NB) ? g_bsum[t] : 0;
    sh[t] = v;
    __syncthreads();
    for (int off = 1; off < 256; off <<= 1) {
        int u = (t >= off) ? sh[t - off] : 0;
        __syncthreads();
        sh[t] += u;
        __syncthreads();
    }
    if (t < SCAN_NB) g_boff[t] = sh[t] - v;
    if (t == 255) g_rowptr[NN] = sh[255];
}

__global__ __launch_bounds__(SCAN_T) void k_scanC() {
    __shared__ int sh[SCAN_T];
    int b = blockIdx.x, t = threadIdx.x;
    int i = b * SCAN_T + t;
    int v = (i < NN) ? g_ecnt[i] : 0;
    sh[t] = v;
    __syncthreads();
    for (int off = 1; off < SCAN_T; off <<= 1) {
        int u = (t >= off) ? sh[t - off] : 0;
        __syncthreads();
        sh[t] += u;
        __syncthreads();
    }
    if (i < NN) g_rowptr[i] = g_boff[b] + sh[t] - v;
}

__global__ __launch_bounds__(256) void k_fill(const int* __restrict__ src,
                                              const int* __restrict__ dst,
                                              const float* __restrict__ w) {
    int e = blockIdx.x * blockDim.x + threadIdx.x;
    if (e < EE) {
        int s = src[e], d = dst[e];
        float nrm = g_dinv[s] * w[e] * g_dinv[d];
        int pos = g_rowptr[d] + atomicAdd(&g_fill[d], 1);
        g_cmeta[pos] = make_int2(s, __float_as_int(nrm));
    }
}

// ---------------------------------------------------------------------------
// Warp-level gather of one node's aggregated row (2 cols per lane).
__device__ __forceinline__ void gather_node(const float* __restrict__ xw,
                                            int n, int lane,
                                            const float* __restrict__ bias,
                                            float& a0, float& a1) {
    int beg = g_rowptr[n], end = g_rowptr[n + 1];
    float b0 = 0.f, b1 = 0.f, c0 = 0.f, c1 = 0.f, d0 = 0.f, d1 = 0.f;
    a0 = 0.f; a1 = 0.f;
    for (int cb = beg; cb < end; cb += 32) {
        int m = end - cb; if (m > 32) m = 32;
        int sreg = 0; float vreg = 0.f;
        if (lane < m) {
            int2 mv = g_cmeta[cb + lane];
            sreg = mv.x; vreg = __int_as_float(mv.y);
        }
        int j = 0;
        for (; j + 3 < m; j += 4) {
            int s0 = __shfl_sync(~0u, sreg, j);
            int s1 = __shfl_sync(~0u, sreg, j + 1);
            int s2 = __shfl_sync(~0u, sreg, j + 2);
            int s3 = __shfl_sync(~0u, sreg, j + 3);
            float v0 = __shfl_sync(~0u, vreg, j);
            float v1 = __shfl_sync(~0u, vreg, j + 1);
            float v2 = __shfl_sync(~0u, vreg, j + 2);
            float v3 = __shfl_sync(~0u, vreg, j + 3);
            float2 x0 = *(const float2*)(xw + (size_t)s0 * 64 + lane * 2);
            float2 x1 = *(const float2*)(xw + (size_t)s1 * 64 + lane * 2);
            float2 x2 = *(const float2*)(xw + (size_t)s2 * 64 + lane * 2);
            float2 x3 = *(const float2*)(xw + (size_t)s3 * 64 + lane * 2);
            a0 += v0 * x0.x; a1 += v0 * x0.y;
            b0 += v1 * x1.x; b1 += v1 * x1.y;
            c0 += v2 * x2.x; c1 += v2 * x2.y;
            d0 += v3 * x3.x; d1 += v3 * x3.y;
        }
        for (; j < m; j++) {
            int s = __shfl_sync(~0u, sreg, j);
            float v = __shfl_sync(~0u, vreg, j);
            float2 xv = *(const float2*)(xw + (size_t)s * 64 + lane * 2);
            a0 += v * xv.x; a1 += v * xv.y;
        }
    }
    a0 += b0 + c0; a0 += d0;
    a1 += b1 + c1; a1 += d1;
    float di = g_dinv[n];
    float sl = 2.0f * di * di;
    float2 xwn = *(const float2*)(xw + (size_t)n * 64 + lane * 2);
    a0 += sl * xwn.x + bias[lane * 2 + 0];
    a1 += sl * xwn.y + bias[lane * 2 + 1];
}

// ---------------------------------------------------------------------------
// Standalone GEMM (layer 1 only): out = in @ W. 64x64 tile, 4x4 micro-tile.
__global__ __launch_bounds__(256) void k_gemm64(const float* __restrict__ in,
                                                const float* __restrict__ W,
                                                float* __restrict__ out) {
    __shared__ float Ws[64 * 64];
    __shared__ float XsT[64][65];
    int tid = threadIdx.x;
    int base = blockIdx.x * 64;
    for (int i = tid; i < 4096; i += 256) Ws[i] = W[i];
    for (int idx = tid; idx < 4096; idx += 256) {
        int r = idx >> 6, c = idx & 63;
        int row = base + r;
        XsT[c][r] = (row < NN) ? in[row * 64 + c] : 0.f;
    }
    __syncthreads();
    int tr = tid >> 4, tc = tid & 15;
    float acc[4][4] = {};
#pragma unroll
    for (int k = 0; k < 64; k++) {
        float x0 = XsT[k][tr * 4 + 0];
        float x1 = XsT[k][tr * 4 + 1];
        float x2 = XsT[k][tr * 4 + 2];
        float x3 = XsT[k][tr * 4 + 3];
        float4 wv = *(const float4*)&Ws[k * 64 + tc * 4];
        acc[0][0] += x0 * wv.x; acc[0][1] += x0 * wv.y;
        acc[0][2] += x0 * wv.z; acc[0][3] += x0 * wv.w;
        acc[1][0] += x1 * wv.x; acc[1][1] += x1 * wv.y;
        acc[1][2] += x1 * wv.z; acc[1][3] += x1 * wv.w;
        acc[2][0] += x2 * wv.x; acc[2][1] += x2 * wv.y;
        acc[2][2] += x2 * wv.z; acc[2][3] += x2 * wv.w;
        acc[3][0] += x3 * wv.x; acc[3][1] += x3 * wv.y;
        acc[3][2] += x3 * wv.z; acc[3][3] += x3 * wv.w;
    }
#pragma unroll
    for (int i = 0; i < 4; i++) {
        int row = base + tr * 4 + i;
        if (row < NN)
            *(float4*)&out[row * 64 + tc * 4] =
                make_float4(acc[i][0], acc[i][1], acc[i][2], acc[i][3]);
    }
}

// ---------------------------------------------------------------------------
// Fused: h = relu(agg(xw_in) + self + bias); xw_out = h @ W.  64 nodes/block.
__global__ __launch_bounds__(256) void k_fused(const float* __restrict__ xw_in,
                                               float* __restrict__ xw_out,
                                               const float* __restrict__ bias,
                                               const float* __restrict__ W) {
    __shared__ float Ws[64 * 64];
    __shared__ float XsT[64][65];
    int tid = threadIdx.x;
    int wrp = tid >> 5, lane = tid & 31;
    int base = blockIdx.x * 64;
    for (int i = tid; i < 4096; i += 256) Ws[i] = W[i];
    // gather phase: warp w handles rows w*8 .. w*8+7
#pragma unroll 1
    for (int i = 0; i < 8; i++) {
        int r = wrp * 8 + i;
        int n = base + r;
        float a0 = 0.f, a1 = 0.f;
        if (n < NN) gather_node(xw_in, n, lane, bias, a0, a1);
        XsT[lane * 2 + 0][r] = fmaxf(a0, 0.f);
        XsT[lane * 2 + 1][r] = fmaxf(a1, 0.f);
    }
    __syncthreads();
    int tr = tid >> 4, tc = tid & 15;
    float acc[4][4] = {};
#pragma unroll
    for (int k = 0; k < 64; k++) {
        float x0 = XsT[k][tr * 4 + 0];
        float x1 = XsT[k][tr * 4 + 1];
        float x2 = XsT[k][tr * 4 + 2];
        float x3 = XsT[k][tr * 4 + 3];
        float4 wv = *(const float4*)&Ws[k * 64 + tc * 4];
        acc[0][0] += x0 * wv.x; acc[0][1] += x0 * wv.y;
        acc[0][2] += x0 * wv.z; acc[0][3] += x0 * wv.w;
        acc[1][0] += x1 * wv.x; acc[1][1] += x1 * wv.y;
        acc[1][2] += x1 * wv.z; acc[1][3] += x1 * wv.w;
        acc[2][0] += x2 * wv.x; acc[2][1] += x2 * wv.y;
        acc[2][2] += x2 * wv.z; acc[2][3] += x2 * wv.w;
        acc[3][0] += x3 * wv.x; acc[3][1] += x3 * wv.y;
        acc[3][2] += x3 * wv.z; acc[3][3] += x3 * wv.w;
    }
#pragma unroll
    for (int i = 0; i < 4; i++) {
        int row = base + tr * 4 + i;
        if (row < NN)
            *(float4*)&xw_out[row * 64 + tc * 4] =
                make_float4(acc[i][0], acc[i][1], acc[i][2], acc[i][3]);
    }
}

// ---------------------------------------------------------------------------
// Final gather (layer 3): h3 row -> classifier partials into per-graph logits.
__global__ __launch_bounds__(256) void k_gatherF(const float* __restrict__ xw,
                                                 const float* __restrict__ bias,
                                                 const int* __restrict__ batch,
                                                 const float* __restrict__ Wl) {
    int wid = (blockIdx.x * blockDim.x + threadIdx.x) >> 5;
    int lane = threadIdx.x & 31;
    if (wid >= NN) return;
    float a0, a1;
    gather_node(xw, wid, lane, bias, a0, a1);
    int j0 = lane * 2, j1 = lane * 2 + 1;
    float l0 = a0 * Wl[j0 * CC + 0] + a1 * Wl[j1 * CC + 0];
    float l1 = a0 * Wl[j0 * CC + 1] + a1 * Wl[j1 * CC + 1];
#pragma unroll
    for (int off = 16; off; off >>= 1) {
        l0 += __shfl_xor_sync(0xffffffffu, l0, off);
        l1 += __shfl_xor_sync(0xffffffffu, l1, off);
    }
    if (lane == 0) {
        int g = batch[wid];
        atomicAdd(&g_plog[g * CC + 0], l0);
        atomicAdd(&g_plog[g * CC + 1], l1);
    }
}

__global__ __launch_bounds__(256) void k_final(const float* __restrict__ bl,
                                               float* __restrict__ out) {
    int i = blockIdx.x * blockDim.x + threadIdx.x;
    if (i < GG * CC) {
        int g = i / CC, c = i % CC;
        out[i] = g_plog[i] / fmaxf(g_cnt[g], 1.0f) + bl[c];
    }
}

extern "C" void kernel_launch(void* const* d_in, const int* in_sizes, int n_in,
                              void* d_out, int out_size) {
    const float* x     = (const float*)d_in[0];
    const int*   ei    = (const int*)d_in[1];
    const float* w     = (const float*)d_in[2];
    const int*   batch = (const int*)d_in[3];
    const float* W1    = (const float*)d_in[4];
    const float* b1    = (const float*)d_in[5];
    const float* W2    = (const float*)d_in[6];
    const float* b2    = (const float*)d_in[7];
    const float* W3    = (const float*)d_in[8];
    const float* b3    = (const float*)d_in[9];
    const float* Wl    = (const float*)d_in[10];
    const float* bl    = (const float*)d_in[11];
    float* out = (float*)d_out;

    const int* src = ei;
    const int* dst = ei + EE;

    float* A;  cudaGetSymbolAddress((void**)&A, g_bufA);
    float* B;  cudaGetSymbolAddress((void**)&B, g_bufB);

    const int eb = (EE + 255) / 256;
    const int nb = (NN + 255) / 256;
    const int gemm_b = (NN + 63) / 64;
    const int gath_b = (NN * 32 + 255) / 256;

    // CSR + normalization build (reused by all 3 layers)
    k_zero<<<nb, 256>>>();
    k_deg<<<eb, 256>>>(dst, w);
    k_dinv<<<nb, 256>>>(batch);
    k_scanA<<<SCAN_NB, SCAN_T>>>();
    k_scanB<<<1, 256>>>();
    k_scanC<<<SCAN_NB, SCAN_T>>>();
    k_fill<<<eb, 256>>>(src, dst, w);

    // layer 1: xw1 = x @ W1 -> A
    k_gemm64<<<gemm_b, 256>>>(x, W1, A);
    // layer 2 fused: h1 = relu(agg(A)+b1); xw2 = h1 @ W2 -> B
    k_fused<<<gemm_b, 256>>>(A, B, b1, W2);
    // layer 3 fused: h2 = relu(agg(B)+b2); xw3 = h2 @ W3 -> A
    k_fused<<<gemm_b, 256>>>(B, A, b2, W3);
    // layer 3 gather + pool + classifier
    k_gatherF<<<gath_b, 256>>>(A, b3, batch, Wl);

    k_final<<<(GG * CC + 255) / 256, 256>>>(bl, out);
}

// round 11
// speedup vs baseline: 2.7787x; 1.2112x over previous
#include <cuda_runtime.h>
#include <cuda_fp16.h>

#define NN 100000
#define EE 1000000
#define HH 64
#define GG 512
#define CC 2

#define SCAN_T 512
#define SCAN_NB ((NN + SCAN_T - 1) / SCAN_T)   // 196

// Scratch (device globals; no allocations allowed)
__device__ __half g_bufA[NN * HH];     // xw (fp16)
__device__ __half g_bufB[NN * HH];     // xw (fp16)
__device__ float g_y[NN * CC];         // y = h2 @ (W3@Wl)
__device__ float g_dinv[NN];
__device__ float g_deg[NN];
__device__ int   g_ecnt[NN];
__device__ int   g_fill[NN];
__device__ int   g_rowptr[NN + 1];
__device__ int2  g_cmeta[EE];          // (src, norm float bits) per edge
__device__ float g_cnt[GG];
__device__ float g_plog[GG * CC];
__device__ float g_M[HH * CC];         // W3 @ Wl
__device__ float g_bWl[CC];            // b3 @ Wl
__device__ int   g_bsum[SCAN_NB];
__device__ int   g_boff[SCAN_NB];

// ---------------------------------------------------------------------------
// zero accumulators + (block 0) precompute M = W3@Wl and b3@Wl
__global__ __launch_bounds__(256) void k_zero(const float* __restrict__ W3,
                                              const float* __restrict__ Wl,
                                              const float* __restrict__ b3) {
    int i = blockIdx.x * blockDim.x + threadIdx.x;
    if (i < NN) { g_deg[i] = 0.f; g_ecnt[i] = 0; g_fill[i] = 0; }
    if (i < GG) g_cnt[i] = 0.f;
    if (i < GG * CC) g_plog[i] = 0.f;
    if (blockIdx.x == 0) {
        int t = threadIdx.x;
        if (t < HH * CC) {
            int k = t >> 1, c = t & 1;
            float acc = 0.f;
#pragma unroll
            for (int j = 0; j < HH; j++) acc += W3[k * HH + j] * Wl[j * CC + c];
            g_M[t] = acc;
        } else if (t < HH * CC + CC) {
            int c = t - HH * CC;
            float acc = 0.f;
#pragma unroll
            for (int j = 0; j < HH; j++) acc += b3[j] * Wl[j * CC + c];
            g_bWl[c] = acc;
        }
    }
}

__global__ __launch_bounds__(256) void k_deg(const int* __restrict__ dst,
                                             const float* __restrict__ w) {
    int e = blockIdx.x * blockDim.x + threadIdx.x;
    if (e < EE) {
        int d = dst[e];
        atomicAdd(&g_deg[d], w[e]);
        atomicAdd(&g_ecnt[d], 1);
    }
}

__global__ __launch_bounds__(256) void k_dinv(const int* __restrict__ batch) {
    int n = blockIdx.x * blockDim.x + threadIdx.x;
    if (n < NN) {
        g_dinv[n] = rsqrtf(g_deg[n] + 2.0f);
        atomicAdd(&g_cnt[batch[n]], 1.0f);
    }
}

// scan: per-block reduce -> scan of partials -> local scan + offset
__global__ __launch_bounds__(SCAN_T) void k_scanA() {
    __shared__ int sh[SCAN_T / 32];
    int b = blockIdx.x, t = threadIdx.x;
    int i = b * SCAN_T + t;
    int v = (i < NN) ? g_ecnt[i] : 0;
#pragma unroll
    for (int off = 16; off; off >>= 1) v += __shfl_xor_sync(~0u, v, off);
    if ((t & 31) == 0) sh[t >> 5] = v;
    __syncthreads();
    if (t < SCAN_T / 32) {
        int s = sh[t];
#pragma unroll
        for (int off = SCAN_T / 64; off; off >>= 1)
            s += __shfl_xor_sync(0xffffu, s, off);
        if (t == 0) g_bsum[b] = s;
    }
}

__global__ __launch_bounds__(256) void k_scanB() {
    __shared__ int sh[256];
    int t = threadIdx.x;
    int v = (t < SCAN_NB) ? g_bsum[t] : 0;
    sh[t] = v;
    __syncthreads();
    for (int off = 1; off < 256; off <<= 1) {
        int u = (t >= off) ? sh[t - off] : 0;
        __syncthreads();
        sh[t] += u;
        __syncthreads();
    }
    if (t < SCAN_NB) g_boff[t] = sh[t] - v;
    if (t == 255) g_rowptr[NN] = sh[255];
}

__global__ __launch_bounds__(SCAN_T) void k_scanC() {
    __shared__ int sh[SCAN_T];
    int b = blockIdx.x, t = threadIdx.x;
    int i = b * SCAN_T + t;
    int v = (i < NN) ? g_ecnt[i] : 0;
    sh[t] = v;
    __syncthreads();
    for (int off = 1; off < SCAN_T; off <<= 1) {
        int u = (t >= off) ? sh[t - off] : 0;
        __syncthreads();
        sh[t] += u;
        __syncthreads();
    }
    if (i < NN) g_rowptr[i] = g_boff[b] + sh[t] - v;
}

__global__ __launch_bounds__(256) void k_fill(const int* __restrict__ src,
                                              const int* __restrict__ dst,
                                              const float* __restrict__ w) {
    int e = blockIdx.x * blockDim.x + threadIdx.x;
    if (e < EE) {
        int s = src[e], d = dst[e];
        float nrm = g_dinv[s] * w[e] * g_dinv[d];
        int pos = g_rowptr[d] + atomicAdd(&g_fill[d], 1);
        g_cmeta[pos] = make_int2(s, __float_as_int(nrm));
    }
}

// ---------------------------------------------------------------------------
// Warp-level gather of one node's aggregated row from fp16 xw (2 cols/lane).
__device__ __forceinline__ void gather_node(const __half* __restrict__ xw,
                                            int n, int lane,
                                            const float* __restrict__ bias,
                                            float& a0, float& a1) {
    int beg = g_rowptr[n], end = g_rowptr[n + 1];
    float b0 = 0.f, b1 = 0.f, c0 = 0.f, c1 = 0.f, d0 = 0.f, d1 = 0.f;
    a0 = 0.f; a1 = 0.f;
    for (int cb = beg; cb < end; cb += 32) {
        int m = end - cb; if (m > 32) m = 32;
        int sreg = 0; float vreg = 0.f;
        if (lane < m) {
            int2 mv = g_cmeta[cb + lane];
            sreg = mv.x; vreg = __int_as_float(mv.y);
        }
        int j = 0;
        for (; j + 3 < m; j += 4) {
            int s0 = __shfl_sync(~0u, sreg, j);
            int s1 = __shfl_sync(~0u, sreg, j + 1);
            int s2 = __shfl_sync(~0u, sreg, j + 2);
            int s3 = __shfl_sync(~0u, sreg, j + 3);
            float v0 = __shfl_sync(~0u, vreg, j);
            float v1 = __shfl_sync(~0u, vreg, j + 1);
            float v2 = __shfl_sync(~0u, vreg, j + 2);
            float v3 = __shfl_sync(~0u, vreg, j + 3);
            float2 x0 = __half22float2(*(const __half2*)(xw + (size_t)s0 * 64 + lane * 2));
            float2 x1 = __half22float2(*(const __half2*)(xw + (size_t)s1 * 64 + lane * 2));
            float2 x2 = __half22float2(*(const __half2*)(xw + (size_t)s2 * 64 + lane * 2));
            float2 x3 = __half22float2(*(const __half2*)(xw + (size_t)s3 * 64 + lane * 2));
            a0 += v0 * x0.x; a1 += v0 * x0.y;
            b0 += v1 * x1.x; b1 += v1 * x1.y;
            c0 += v2 * x2.x; c1 += v2 * x2.y;
            d0 += v3 * x3.x; d1 += v3 * x3.y;
        }
        for (; j < m; j++) {
            int s = __shfl_sync(~0u, sreg, j);
            float v = __shfl_sync(~0u, vreg, j);
            float2 xv = __half22float2(*(const __half2*)(xw + (size_t)s * 64 + lane * 2));
            a0 += v * xv.x; a1 += v * xv.y;
        }
    }
    a0 += b0 + c0; a0 += d0;
    a1 += b1 + c1; a1 += d1;
    float di = g_dinv[n];
    float sl = 2.0f * di * di;
    float2 xwn = __half22float2(*(const __half2*)(xw + (size_t)n * 64 + lane * 2));
    a0 += sl * xwn.x + bias[lane * 2 + 0];
    a1 += sl * xwn.y + bias[lane * 2 + 1];
}

__device__ __forceinline__ void store_h4(__half* __restrict__ out, size_t off,
                                         float a, float b, float c, float d) {
    __half2 h01 = __floats2half2_rn(a, b);
    __half2 h23 = __floats2half2_rn(c, d);
    uint2 pk;
    pk.x = *reinterpret_cast<unsigned*>(&h01);
    pk.y = *reinterpret_cast<unsigned*>(&h23);
    *reinterpret_cast<uint2*>(out + off) = pk;
}

// ---------------------------------------------------------------------------
// Layer-1 GEMM: out(fp16) = in @ W.  64x64 tile, 4x4 micro-tile.
__global__ __launch_bounds__(256) void k_gemm64(const float* __restrict__ in,
                                                const float* __restrict__ W,
                                                __half* __restrict__ out) {
    __shared__ float Ws[64 * 64];
    __shared__ float XsT[64][65];
    int tid = threadIdx.x;
    int base = blockIdx.x * 64;
    for (int i = tid; i < 4096; i += 256) Ws[i] = W[i];
    for (int idx = tid; idx < 4096; idx += 256) {
        int r = idx >> 6, c = idx & 63;
        int row = base + r;
        XsT[c][r] = (row < NN) ? in[row * 64 + c] : 0.f;
    }
    __syncthreads();
    int tr = tid >> 4, tc = tid & 15;
    float acc[4][4] = {};
#pragma unroll
    for (int k = 0; k < 64; k++) {
        float x0 = XsT[k][tr * 4 + 0];
        float x1 = XsT[k][tr * 4 + 1];
        float x2 = XsT[k][tr * 4 + 2];
        float x3 = XsT[k][tr * 4 + 3];
        float4 wv = *(const float4*)&Ws[k * 64 + tc * 4];
        acc[0][0] += x0 * wv.x; acc[0][1] += x0 * wv.y;
        acc[0][2] += x0 * wv.z; acc[0][3] += x0 * wv.w;
        acc[1][0] += x1 * wv.x; acc[1][1] += x1 * wv.y;
        acc[1][2] += x1 * wv.z; acc[1][3] += x1 * wv.w;
        acc[2][0] += x2 * wv.x; acc[2][1] += x2 * wv.y;
        acc[2][2] += x2 * wv.z; acc[2][3] += x2 * wv.w;
        acc[3][0] += x3 * wv.x; acc[3][1] += x3 * wv.y;
        acc[3][2] += x3 * wv.z; acc[3][3] += x3 * wv.w;
    }
#pragma unroll
    for (int i = 0; i < 4; i++) {
        int row = base + tr * 4 + i;
        if (row < NN)
            store_h4(out, (size_t)row * 64 + tc * 4,
                     acc[i][0], acc[i][1], acc[i][2], acc[i][3]);
    }
}

// ---------------------------------------------------------------------------
// Fused: h = relu(agg(xw_in)+self+bias); xw_out(fp16) = h @ W.  64 nodes/block.
__global__ __launch_bounds__(256) void k_fused(const __half* __restrict__ xw_in,
                                               __half* __restrict__ xw_out,
                                               const float* __restrict__ bias,
                                               const float* __restrict__ W) {
    __shared__ float Ws[64 * 64];
    __shared__ float XsT[64][65];
    int tid = threadIdx.x;
    int wrp = tid >> 5, lane = tid & 31;
    int base = blockIdx.x * 64;
    for (int i = tid; i < 4096; i += 256) Ws[i] = W[i];
#pragma unroll 1
    for (int i = 0; i < 8; i++) {
        int r = wrp * 8 + i;
        int n = base + r;
        float a0 = 0.f, a1 = 0.f;
        if (n < NN) gather_node(xw_in, n, lane, bias, a0, a1);
        XsT[lane * 2 + 0][r] = fmaxf(a0, 0.f);
        XsT[lane * 2 + 1][r] = fmaxf(a1, 0.f);
    }
    __syncthreads();
    int tr = tid >> 4, tc = tid & 15;
    float acc[4][4] = {};
#pragma unroll
    for (int k = 0; k < 64; k++) {
        float x0 = XsT[k][tr * 4 + 0];
        float x1 = XsT[k][tr * 4 + 1];
        float x2 = XsT[k][tr * 4 + 2];
        float x3 = XsT[k][tr * 4 + 3];
        float4 wv = *(const float4*)&Ws[k * 64 + tc * 4];
        acc[0][0] += x0 * wv.x; acc[0][1] += x0 * wv.y;
        acc[0][2] += x0 * wv.z; acc[0][3] += x0 * wv.w;
        acc[1][0] += x1 * wv.x; acc[1][1] += x1 * wv.y;
        acc[1][2] += x1 * wv.z; acc[1][3] += x1 * wv.w;
        acc[2][0] += x2 * wv.x; acc[2][1] += x2 * wv.y;
        acc[2][2] += x2 * wv.z; acc[2][3] += x2 * wv.w;
        acc[3][0] += x3 * wv.x; acc[3][1] += x3 * wv.y;
        acc[3][2] += x3 * wv.z; acc[3][3] += x3 * wv.w;
    }
#pragma unroll
    for (int i = 0; i < 4; i++) {
        int row = base + tr * 4 + i;
        if (row < NN)
            store_h4(xw_out, (size_t)row * 64 + tc * 4,
                     acc[i][0], acc[i][1], acc[i][2], acc[i][3]);
    }
}

// ---------------------------------------------------------------------------
// Layer-3 reduced: h2 = relu(agg(xw_in)+self+b2); y = h2 @ M  (M = W3@Wl, 64x2)
__global__ __launch_bounds__(256) void k_fused_y(const __half* __restrict__ xw_in,
                                                 const float* __restrict__ bias) {
    int wid = (blockIdx.x * blockDim.x + threadIdx.x) >> 5;
    int lane = threadIdx.x & 31;
    if (wid >= NN) return;
    float a0, a1;
    gather_node(xw_in, wid, lane, bias, a0, a1);
    a0 = fmaxf(a0, 0.f);
    a1 = fmaxf(a1, 0.f);
    int j0 = lane * 2, j1 = lane * 2 + 1;
    float y0 = a0 * g_M[j0 * CC + 0] + a1 * g_M[j1 * CC + 0];
    float y1 = a0 * g_M[j0 * CC + 1] + a1 * g_M[j1 * CC + 1];
#pragma unroll
    for (int off = 16; off; off >>= 1) {
        y0 += __shfl_xor_sync(0xffffffffu, y0, off);
        y1 += __shfl_xor_sync(0xffffffffu, y1, off);
    }
    if (lane == 0) *(float2*)&g_y[wid * CC] = make_float2(y0, y1);
}

// ---------------------------------------------------------------------------
// Edge pass in y-space: t[n] = sum cval*y[src] + sl*y[n]; atomic into plog.
__global__ __launch_bounds__(256) void k_edge(const int* __restrict__ batch) {
    int wid = (blockIdx.x * blockDim.x + threadIdx.x) >> 5;
    int lane = threadIdx.x & 31;
    if (wid >= NN) return;
    int n = wid;
    int beg = g_rowptr[n], end = g_rowptr[n + 1];
    float l0 = 0.f, l1 = 0.f;
    for (int cb = beg + lane; cb < end; cb += 32) {
        int2 mv = g_cmeta[cb];
        float v = __int_as_float(mv.y);
        float2 yv = *(const float2*)&g_y[mv.x * CC];
        l0 += v * yv.x;
        l1 += v * yv.y;
    }
#pragma unroll
    for (int off = 16; off; off >>= 1) {
        l0 += __shfl_xor_sync(0xffffffffu, l0, off);
        l1 += __shfl_xor_sync(0xffffffffu, l1, off);
    }
    if (lane == 0) {
        float di = g_dinv[n];
        float sl = 2.0f * di * di;
        float2 yn = *(const float2*)&g_y[n * CC];
        l0 += sl * yn.x;
        l1 += sl * yn.y;
        int g = batch[n];
        atomicAdd(&g_plog[g * CC + 0], l0);
        atomicAdd(&g_plog[g * CC + 1], l1);
    }
}

__global__ __launch_bounds__(256) void k_final(const float* __restrict__ bl,
                                               float* __restrict__ out) {
    int i = blockIdx.x * blockDim.x + threadIdx.x;
    if (i < GG * CC) {
        int g = i / CC, c = i % CC;
        float cnt = g_cnt[g];
        out[i] = (cnt > 0.f) ? g_plog[i] / cnt + g_bWl[c] + bl[c] : bl[c];
    }
}

extern "C" void kernel_launch(void* const* d_in, const int* in_sizes, int n_in,
                              void* d_out, int out_size) {
    const float* x     = (const float*)d_in[0];
    const int*   ei    = (const int*)d_in[1];
    const float* w     = (const float*)d_in[2];
    const int*   batch = (const int*)d_in[3];
    const float* W1    = (const float*)d_in[4];
    const float* b1    = (const float*)d_in[5];
    const float* W2    = (const float*)d_in[6];
    const float* b2    = (const float*)d_in[7];
    const float* W3    = (const float*)d_in[8];
    const float* b3    = (const float*)d_in[9];
    const float* Wl    = (const float*)d_in[10];
    const float* bl    = (const float*)d_in[11];
    float* out = (float*)d_out;

    const int* src = ei;
    const int* dst = ei + EE;

    __half* A;  cudaGetSymbolAddress((void**)&A, g_bufA);
    __half* B;  cudaGetSymbolAddress((void**)&B, g_bufB);

    const int eb = (EE + 255) / 256;
    const int nb = (NN + 255) / 256;
    const int gemm_b = (NN + 63) / 64;
    const int warp_b = (NN * 32 + 255) / 256;

    // CSR + normalization build (reused by all 3 layers)
    k_zero<<<nb, 256>>>(W3, Wl, b3);
    k_deg<<<eb, 256>>>(dst, w);
    k_dinv<<<nb, 256>>>(batch);
    k_scanA<<<SCAN_NB, SCAN_T>>>();
    k_scanB<<<1, 256>>>();
    k_scanC<<<SCAN_NB, SCAN_T>>>();
    k_fill<<<eb, 256>>>(src, dst, w);

    // layer 1: xw1 = x @ W1 -> A (fp16)
    k_gemm64<<<gemm_b, 256>>>(x, W1, A);
    // layer 2 fused: h1 = relu(agg(A)+b1); xw2 = h1 @ W2 -> B (fp16)
    k_fused<<<gemm_b, 256>>>(A, B, b1, W2);
    // layer 3 reduced: h2 = relu(agg(B)+b2); y = h2 @ (W3@Wl)
    k_fused_y<<<warp_b, 256>>>(B, b2);
    // edge pass in y-space + pool
    k_edge<<<warp_b, 256>>>(batch);

    k_final<<<(GG * CC + 255) / 256, 256>>>(bl, out);
}